// round 3
// baseline (speedup 1.0000x reference)
#include <cuda_runtime.h>
#include <cuda_bf16.h>
#include <stdint.h>

// ---------------------------------------------------------------------------
// Exact Chamfer via uniform-grid nearest neighbor.
//   Bin both point sets into a 16^3 grid over [-4,4]^3 (cell 0.5) with a
//   counting sort (hist -> prefix -> scatter, points stored cell-contiguous
//   as float4). One warp per query walks Chebyshev shells around its cell,
//   pruning cells by exact box distance (edge cells extend to infinity so
//   clamped outliers are handled exactly) and terminating when
//   ((r-1)*CELL)^2 >= current min  (valid lower bound for shell r).
//   Exact: identical min-set as brute force. fp min is order-independent,
//   final reduction is fixed-order -> deterministic output.
//   Work drops 536M pairs -> ~10-20M.
// ---------------------------------------------------------------------------

#define NPTS   16384
#define G      16
#define NC     (G*G*G)          // 4096 cells
#define CELLF  0.5f
#define GMINF  (-4.0f)
#define INVC   2.0f

__device__ int    g_cnt[2][NC];      // zero-init at load; re-zeroed by reduce
__device__ int    g_off[2][NC];
__device__ int    g_cur[2][NC];
__device__ float4 g_pts[2][NPTS];
__device__ float  g_dmin[2 * NPTS];

__device__ __forceinline__ int cell_of(float v) {
    int c = (int)floorf((v - GMINF) * INVC);
    return min(G - 1, max(0, c));
}

__global__ void hist_kernel(const float* __restrict__ pa,
                            const float* __restrict__ pb) {
    int t = blockIdx.x * blockDim.x + threadIdx.x;   // 0..32767
    int arr = t >> 14, i = t & (NPTS - 1);
    const float* s = arr ? pb : pa;
    int cx = cell_of(s[3 * i + 0]);
    int cy = cell_of(s[3 * i + 1]);
    int cz = cell_of(s[3 * i + 2]);
    atomicAdd(&g_cnt[arr][(cz * G + cy) * G + cx], 1);
}

__global__ void prefix_kernel() {   // one CTA per array
    __shared__ int sm[1024];
    const int arr = blockIdx.x, tid = threadIdx.x;
    const int base = tid * 4;
    int c0 = g_cnt[arr][base + 0], c1 = g_cnt[arr][base + 1];
    int c2 = g_cnt[arr][base + 2], c3 = g_cnt[arr][base + 3];
    int tot = c0 + c1 + c2 + c3;
    sm[tid] = tot;
    __syncthreads();
    for (int off = 1; off < 1024; off <<= 1) {   // Hillis-Steele inclusive
        int v = sm[tid];
        int add = (tid >= off) ? sm[tid - off] : 0;
        __syncthreads();
        sm[tid] = v + add;
        __syncthreads();
    }
    int o0 = sm[tid] - tot;
    int o1 = o0 + c0, o2 = o1 + c1, o3 = o2 + c2;
    g_off[arr][base + 0] = o0; g_off[arr][base + 1] = o1;
    g_off[arr][base + 2] = o2; g_off[arr][base + 3] = o3;
    g_cur[arr][base + 0] = o0; g_cur[arr][base + 1] = o1;
    g_cur[arr][base + 2] = o2; g_cur[arr][base + 3] = o3;
}

__global__ void scatter_kernel(const float* __restrict__ pa,
                               const float* __restrict__ pb) {
    int t = blockIdx.x * blockDim.x + threadIdx.x;
    int arr = t >> 14, i = t & (NPTS - 1);
    const float* s = arr ? pb : pa;
    float x = s[3 * i + 0], y = s[3 * i + 1], z = s[3 * i + 2];
    int ci = (cell_of(z) * G + cell_of(y)) * G + cell_of(x);
    int pos = atomicAdd(&g_cur[arr][ci], 1);
    g_pts[arr][pos] = make_float4(x, y, z, 0.f);
}

__global__ __launch_bounds__(256)
void query_kernel(const float* __restrict__ pa, const float* __restrict__ pb) {
    const int w    = blockIdx.x * 8 + (threadIdx.x >> 5);   // 0..32767
    const int lane = threadIdx.x & 31;
    const int arr  = w >> 14;           // query set
    const int qi   = w & (NPTS - 1);
    const float* qs = arr ? pb : pa;
    const float qx = qs[3 * qi + 0];
    const float qy = qs[3 * qi + 1];
    const float qz = qs[3 * qi + 2];
    const int ga = 1 - arr;             // grid being searched
    const int cx = cell_of(qx), cy = cell_of(qy), cz = cell_of(qz);

    float lane_min = 3e38f, cur_min = 3e38f;

    for (int r = 0; r < G; ++r) {
        if (r >= 1) {
            float lb = (float)(r - 1) * CELLF;   // lower bound to any shell-r cell
            if (lb * lb >= cur_min) break;
        }
        const int x0 = max(cx - r, 0), x1 = min(cx + r, G - 1);
        const int y0 = max(cy - r, 0), y1 = min(cy + r, G - 1);
        const int z0 = max(cz - r, 0), z1 = min(cz + r, G - 1);

        for (int Z = z0; Z <= z1; ++Z) {
            const int az = (Z > cz) ? (Z - cz) : (cz - Z);
            float lo = GMINF + Z * CELLF, hi = lo + CELLF;
            float bz = 0.f;
            if (qz < lo) { if (Z > 0) bz = lo - qz; }
            else if (qz > hi) { if (Z < G - 1) bz = qz - hi; }
            const float bz2 = bz * bz;

            for (int Y = y0; Y <= y1; ++Y) {
                const int ay = (Y > cy) ? (Y - cy) : (cy - Y);
                const bool inner_yz = (az < r) && (ay < r);
                lo = GMINF + Y * CELLF; hi = lo + CELLF;
                float by = 0.f;
                if (qy < lo) { if (Y > 0) by = lo - qy; }
                else if (qy > hi) { if (Y < G - 1) by = qy - hi; }
                const float byz2 = fmaf(by, by, bz2);
                if (byz2 >= cur_min) continue;

                for (int X = x0; X <= x1; ++X) {
                    const int ax = (X > cx) ? (X - cx) : (cx - X);
                    if (inner_yz && ax < r) continue;   // scanned at smaller r
                    lo = GMINF + X * CELLF; hi = lo + CELLF;
                    float bx = 0.f;
                    if (qx < lo) { if (X > 0) bx = lo - qx; }
                    else if (qx > hi) { if (X < G - 1) bx = qx - hi; }
                    const float bd2 = fmaf(bx, bx, byz2);
                    if (bd2 >= cur_min) continue;

                    const int ci = (Z * G + Y) * G + X;
                    const int s0 = __ldg(&g_off[ga][ci]);
                    const int e0 = s0 + __ldg(&g_cnt[ga][ci]);
                    for (int t = s0 + lane; t < e0; t += 32) {
                        const float4 p = __ldg(&g_pts[ga][t]);
                        const float dx = qx - p.x;
                        const float dy = qy - p.y;
                        const float dz = qz - p.z;
                        lane_min = fminf(lane_min,
                                         fmaf(dx, dx, fmaf(dy, dy, dz * dz)));
                    }
                }
            }
        }
        float m = lane_min;
        #pragma unroll
        for (int o = 16; o; o >>= 1)
            m = fminf(m, __shfl_xor_sync(0xffffffffu, m, o));
        cur_min = m;
    }
    if (lane == 0) g_dmin[arr * NPTS + qi] = cur_min;
}

__global__ void reduce_kernel(float* __restrict__ out) {
    __shared__ double sm[1024];
    const int tid = threadIdx.x;
    double acc = 0.0;
    for (int i = tid; i < 2 * NPTS; i += 1024)
        acc += (double)g_dmin[i];
    sm[tid] = acc;
    __syncthreads();
    for (int o = 512; o; o >>= 1) {
        if (tid < o) sm[tid] += sm[tid + o];
        __syncthreads();
    }
    if (tid == 0) out[0] = (float)(sm[0] * (1.0 / (double)NPTS));
    // re-zero histogram for the next (graph-replayed) run
    int* c = &g_cnt[0][0];
    for (int i = tid; i < 2 * NC; i += 1024) c[i] = 0;
}

extern "C" void kernel_launch(void* const* d_in, const int* in_sizes, int n_in,
                              void* d_out, int out_size) {
    const float* p_hat = (const float*)d_in[0];  // [16384,3]
    const float* p     = (const float*)d_in[1];  // [16384,3]
    float* out = (float*)d_out;

    hist_kernel<<<32, 1024>>>(p_hat, p);
    prefix_kernel<<<2, 1024>>>();
    scatter_kernel<<<32, 1024>>>(p_hat, p);
    query_kernel<<<4096, 256>>>(p_hat, p);
    reduce_kernel<<<1, 1024>>>(out);
}